// round 16
// baseline (speedup 1.0000x reference)
#include <cuda_runtime.h>
#include <cstdint>

#define JAX_PARTITIONABLE 1

#define MAXP   (1024*2048)
#define NBMAX  1024
#define ITERS  1000
#define SUBN   50000
#define CNTB   1000
#define CHUNK  4096          // elements per block (16 per thread)
#define NANF   0x7FC00000u

// ------------------ device scratch (self-cleaning) ------------------
__device__ int          g_n_valid;
__device__ int          g_bc[NBMAX];
__device__ int          g_idx[MAXP];
__device__ float        g_ymask[MAXP];          // y if mask else NaN
__device__ unsigned int g_cand[MAXP];           // compacted candidate keys
__device__ int          g_ccnt;                 // zero invariant
__device__ float        g_xsub[SUBN];
__device__ float        g_ysub[SUBN];
__device__ float        g_scales[ITERS];
__device__ float        g_shifts[ITERS];
__device__ int          g_counts[ITERS];        // zero invariant
__device__ unsigned int g_hist[6][2048];        // zero invariant
__device__ unsigned int g_done[8];              // zero invariant
__device__ unsigned int g_sel_prefix;
__device__ long long    g_sel_rank;
__device__ float        g_med;
__device__ float        g_dyn;
__device__ float        g_s;
__device__ float        g_t;
__device__ float        g_part[NBMAX];

// ------------------ threefry2x32 (bit-exact vs JAX) ------------------
__host__ __device__ __forceinline__ void tf2x32(unsigned int k0, unsigned int k1,
                                                unsigned int x0, unsigned int x1,
                                                unsigned int& o0, unsigned int& o1) {
    unsigned int ks2 = k0 ^ k1 ^ 0x1BD11BDAu;
    x0 += k0; x1 += k1;
#define TF_RND(r) { x0 += x1; x1 = (x1 << (r)) | (x1 >> (32 - (r))); x1 ^= x0; }
    TF_RND(13) TF_RND(15) TF_RND(26) TF_RND(6)
    x0 += k1;  x1 += ks2 + 1u;
    TF_RND(17) TF_RND(29) TF_RND(16) TF_RND(24)
    x0 += ks2; x1 += k0 + 2u;
    TF_RND(13) TF_RND(15) TF_RND(26) TF_RND(6)
    x0 += k0;  x1 += k1 + 3u;
    TF_RND(17) TF_RND(29) TF_RND(16) TF_RND(24)
    x0 += k1;  x1 += ks2 + 4u;
    TF_RND(13) TF_RND(15) TF_RND(26) TF_RND(6)
    x0 += ks2; x1 += k0 + 5u;
#undef TF_RND
    o0 = x0; o1 = x1;
}

__device__ __forceinline__ unsigned int jax_bits(unsigned int ka, unsigned int kb,
                                                 unsigned int e, unsigned int n) {
#if JAX_PARTITIONABLE
    unsigned int a, b;
    tf2x32(ka, kb, 0u, e, a, b);
    return a ^ b;
#else
    unsigned int h = n >> 1;
    unsigned int lane = (e < h) ? e : (e - h);
    unsigned int a, b;
    tf2x32(ka, kb, lane, lane + h, a, b);
    return (e < h) ? a : b;
#endif
}

static inline void jax_split2_host(unsigned int ka, unsigned int kb, unsigned int* o) {
#if JAX_PARTITIONABLE
    unsigned int a, b;
    tf2x32(ka, kb, 0u, 0u, a, b); o[0] = a; o[1] = b;
    tf2x32(ka, kb, 0u, 1u, a, b); o[2] = a; o[3] = b;
#else
    unsigned int a0, b0, a1, b1;
    tf2x32(ka, kb, 0u, 2u, a0, b0);
    tf2x32(ka, kb, 1u, 3u, a1, b1);
    o[0] = a0; o[1] = a1; o[2] = b0; o[3] = b1;
#endif
}

// NaN/inf-safe: isfinite implied (NaN fails both compares, +-inf fails one)
__device__ __forceinline__ bool maskf(float d) {
    return (d > 0.1f) && (d < 100.0f);
}
__device__ __forceinline__ float y_of(float d) {
    return __fdiv_rn(1.0f, __fadd_rn(d, 1e-6f));
}
__device__ __forceinline__ unsigned int randint_off(unsigned int hb, unsigned int lb,
                                                    unsigned int span) {
    unsigned int m = 65536u % span;
    m = (m * m) % span;
    unsigned int off = (hb % span) * m + (lb % span);
    return off % span;
}

// exclusive scan over 256 threads via warp shuffles; wsh = shared int[8]
__device__ __forceinline__ int blk_scan256(int v, int* wsh) {
    int t = threadIdx.x, lane = t & 31, w = t >> 5;
    int incl = v;
#pragma unroll
    for (int off = 1; off < 32; off <<= 1) {
        int x = __shfl_up_sync(0xffffffffu, incl, off);
        if (lane >= off) incl += x;
    }
    if (lane == 31) wsh[w] = incl;
    __syncthreads();
    if (w == 0) {
        int s = (lane < 8) ? wsh[lane] : 0;
#pragma unroll
        for (int off = 1; off < 8; off <<= 1) {
            int x = __shfl_up_sync(0xffffffffu, s, off);
            if (lane >= off) s += x;
        }
        if (lane < 8) wsh[lane] = s;
    }
    __syncthreads();
    return (w ? wsh[w - 1] : 0) + incl - v;
}

__device__ __forceinline__ bool is_last_block(int id, unsigned int grid) {
    __threadfence();
    __shared__ unsigned int s_last;
    if (threadIdx.x == 0)
        s_last = (atomicAdd(&g_done[id], 1u) == grid - 1u) ? 1u : 0u;
    __syncthreads();
    return s_last != 0u;
}

__device__ __forceinline__ void lb_clean(int hi, int doneid, int nb) {
    __syncthreads();
    if (hi >= 0)
        for (int j = threadIdx.x; j < nb; j += 256) g_hist[hi][j] = 0u;
    if (threadIdx.x == 0) g_done[doneid] = 0u;
}

// parallel bin selection over g_hist[hi]; levels 0/1: 2048 bins, level 2: 1024
__device__ void choose_level(int level, int stage, int hi, int P) {
    __shared__ int wsh[8];
    __shared__ int sh_b;
    __shared__ long long sh_e;
    __shared__ int sh_next;
    __shared__ unsigned int sh_tot;
    __shared__ int sh_need;
    __shared__ unsigned int sh_selkey, sh_vb;
    __shared__ unsigned int red[256];

    int t = threadIdx.x;
    int nb = (level == 2) ? 1024 : 2048;
    int per = nb >> 8;
    unsigned int v[8];
    int sum = 0;
#pragma unroll
    for (int j = 0; j < 8; j++) {
        v[j] = (j < per) ? g_hist[hi][t * per + j] : 0u;
        sum += (int)v[j];
    }
    if (t == 0) { sh_b = -1; sh_next = nb; }
    __syncthreads();
    int excl = blk_scan256(sum, wsh);
    if (t == 255) sh_tot = (unsigned int)(excl + sum);
    __syncthreads();
    long long r = g_sel_rank;
    if (r >= (long long)excl && r < (long long)(excl + sum)) {
        long long c = excl;
        for (int j = 0; j < per; j++) {
            if (r < c + (long long)v[j]) { sh_b = t * per + j; sh_e = c; break; }
            c += (long long)v[j];
        }
    }
    __syncthreads();
    int b = sh_b;
    if (level == 2 && b >= 0) {
        for (int j = 0; j < per; j++) {
            int idx = t * per + j;
            if (idx > b && v[j]) { atomicMin(&sh_next, idx); break; }
        }
    }
    __syncthreads();
    if (t == 0) {
        long long e = sh_e;
        int bb = b;
        long long tot = (long long)sh_tot;
        if (bb < 0) { bb = nb - 1; e = tot; }   // degenerate n==0
        long long rl = r - e;
        g_sel_rank = rl;
        if (level == 0) g_sel_prefix = (unsigned int)bb;
        else if (level == 1) g_sel_prefix = (g_sel_prefix << 11) | (unsigned int)bb;
        else {
            unsigned int selkey = (g_sel_prefix << 10) | (unsigned int)bb;
            unsigned int eq = g_hist[hi][bb];
            int n = g_n_valid;
            int need = 0;
            unsigned int vb = selkey;
            if (!(n & 1)) {
                if (rl + 1 < (long long)eq) vb = selkey;
                else if (sh_next < nb)
                    vb = (g_sel_prefix << 10) | (unsigned int)sh_next;
                else need = 1;
            }
            sh_need = need; sh_selkey = selkey; sh_vb = vb;
        }
    }
    __syncthreads();
    if (level != 2) return;

    unsigned int selkey = sh_selkey;
    unsigned int vb;
    if (sh_need) {
        // rare fallback: min key strictly greater than selkey (full ymask scan)
        float med = g_med;
        unsigned int local = 0xFFFFFFFFu;
        for (int i = t; i < P; i += 256) {
            float ym = g_ymask[i];
            unsigned int kraw = __float_as_uint(ym);
            if (kraw >= 0x7F800000u) continue;
            unsigned int key = stage ? (__float_as_uint(__fsub_rn(ym, med)) & 0x7FFFFFFFu)
                                     : kraw;
            if (key > selkey && key < local) local = key;
        }
        red[t] = local;
        __syncthreads();
        for (int off = 128; off; off >>= 1) {
            if (t < off) red[t] = min(red[t], red[t + off]);
            __syncthreads();
        }
        vb = red[0];
    } else vb = sh_vb;

    if (t == 0) {
        int n = g_n_valid;
        float va = __uint_as_float(selkey);
        float med = (n & 1) ? va
            : __fadd_rn(__fmul_rn(va, 0.5f), __fmul_rn(__uint_as_float(vb), 0.5f));
        if (stage == 0) {
            g_med = med;
            g_sel_rank = (n > 0) ? (long long)((n - 1) / 2) : 0ll;
            g_sel_prefix = 0u;
        } else {
            float dyn = __fmul_rn(med, 0.5f);
            if (dyn < 1e-5f) dyn = 0.01f;
            g_dyn = dyn;
        }
    }
}

// ------------------ kernels ------------------
// div pass: y, yout (scalar) + ymask (float4), count, L0s0 hist;
// LB: scan g_bc, set n_valid/rank, choose L0s0, clean
__global__ void __launch_bounds__(256)
k_fused1(const float* __restrict__ dren, float* __restrict__ yout, int P, int NB) {
    __shared__ unsigned int sh[2048];
    __shared__ int wsh[8];
    __shared__ int sh_tot;
    int t = threadIdx.x;
    for (int j = t; j < 2048; j += 256) sh[j] = 0u;
    __syncthreads();
    int s0 = blockIdx.x * CHUNK + t * 16;
    int cnt = 0;
    if (s0 + 16 <= P) {
        float4 q0 = *(const float4*)(dren + s0);
        float4 q1 = *(const float4*)(dren + s0 + 4);
        float4 q2 = *(const float4*)(dren + s0 + 8);
        float4 q3 = *(const float4*)(dren + s0 + 12);
        float dd[16] = {q0.x, q0.y, q0.z, q0.w, q1.x, q1.y, q1.z, q1.w,
                        q2.x, q2.y, q2.z, q2.w, q3.x, q3.y, q3.z, q3.w};
        float ym[16];
#pragma unroll
        for (int k = 0; k < 16; k++) {
            float y = y_of(dd[k]);
            yout[s0 + k] = y;
            bool m = maskf(dd[k]);
            ym[k] = m ? y : __uint_as_float(NANF);
            if (m) { cnt++; atomicAdd(&sh[__float_as_uint(y) >> 21], 1u); }
        }
#pragma unroll
        for (int j = 0; j < 4; j++)
            *(float4*)(g_ymask + s0 + 4 * j) =
                make_float4(ym[4 * j], ym[4 * j + 1], ym[4 * j + 2], ym[4 * j + 3]);
    } else {
        for (int i = s0; i < P && i < s0 + 16; i++) {
            float d = dren[i];
            float y = y_of(d);
            yout[i] = y;
            bool m = maskf(d);
            g_ymask[i] = m ? y : __uint_as_float(NANF);
            if (m) { cnt++; atomicAdd(&sh[__float_as_uint(y) >> 21], 1u); }
        }
    }
    int lane = t & 31, w = t >> 5;
    int v = cnt;
    for (int o = 16; o; o >>= 1) v += __shfl_down_sync(0xffffffffu, v, o);
    if (lane == 0) wsh[w] = v;
    __syncthreads();
    if (t == 0) {
        int s = 0;
        for (int j = 0; j < 8; j++) s += wsh[j];
        g_bc[blockIdx.x] = s;
    }
    __syncthreads();
    for (int j = t; j < 2048; j += 256)
        if (sh[j]) atomicAdd(&g_hist[0][j], sh[j]);

    if (!is_last_block(0, gridDim.x)) return;

    int b4[4]; int s = 0;
#pragma unroll
    for (int j = 0; j < 4; j++) {
        int ii = t * 4 + j;
        b4[j] = (ii < NB) ? g_bc[ii] : 0;
        s += b4[j];
    }
    int ex = blk_scan256(s, wsh);
    int run = ex;
#pragma unroll
    for (int j = 0; j < 4; j++) {
        int ii = t * 4 + j;
        if (ii < NB) g_bc[ii] = run;
        run += b4[j];
    }
    if (t == 255) sh_tot = ex + s;
    __syncthreads();
    if (t == 0) {
        int n = sh_tot;
        g_n_valid = n;
        g_sel_rank = (n > 0) ? (long long)((n - 1) / 2) : 0ll;
        g_sel_prefix = 0u;
    }
    __syncthreads();
    choose_level(0, 0, 0, P);
    lb_clean(0, 0, 2048);
}

// stage0 L1: hist matching L0 prefix + compact matching keys to g_cand
// (+ g_idx scatter if !dense); LB: choose L1s0, clean
__global__ void __launch_bounds__(256)
k_fused2(int P) {
    __shared__ unsigned int sh[2048];
    __shared__ int wsh[8];
    __shared__ int s_base, s_tot;
    int t = threadIdx.x;
    for (int j = t; j < 2048; j += 256) sh[j] = 0u;
    unsigned int prefix = g_sel_prefix;
    bool dense = (g_n_valid == P);
    __syncthreads();
    int s0 = blockIdx.x * CHUNK + t * 16;
    unsigned int key[16];
    if (s0 + 16 <= P) {
#pragma unroll
        for (int j = 0; j < 4; j++) {
            float4 a = *(const float4*)(g_ymask + s0 + 4 * j);
            key[4 * j]     = __float_as_uint(a.x);
            key[4 * j + 1] = __float_as_uint(a.y);
            key[4 * j + 2] = __float_as_uint(a.z);
            key[4 * j + 3] = __float_as_uint(a.w);
        }
    } else {
#pragma unroll
        for (int k = 0; k < 16; k++)
            key[k] = (s0 + k < P) ? __float_as_uint(g_ymask[s0 + k]) : NANF;
    }
    int nm = 0;
    unsigned int mkeys[16];
    int cnt = 0;
    unsigned int bits = 0u;
#pragma unroll
    for (int k = 0; k < 16; k++) {
        if ((key[k] >> 21) == prefix) {
            atomicAdd(&sh[(key[k] >> 10) & 2047u], 1u);
            mkeys[nm++] = key[k];
        }
        if (key[k] < 0x7F800000u) { cnt++; bits |= (1u << k); }
    }
    int mex = blk_scan256(nm, wsh);
    if (t == 255) s_tot = mex + nm;
    __syncthreads();
    if (t == 0) s_base = atomicAdd(&g_ccnt, s_tot);
    __syncthreads();
    for (int j = 0; j < nm; j++) g_cand[s_base + mex + j] = mkeys[j];
    if (!dense) {
        int excl = blk_scan256(cnt, wsh);
        int wpos = g_bc[blockIdx.x] + excl;
#pragma unroll
        for (int k = 0; k < 16; k++)
            if ((bits >> k) & 1u) g_idx[wpos++] = s0 + k;
    }
    __syncthreads();
    for (int j = t; j < 2048; j += 256)
        if (sh[j]) atomicAdd(&g_hist[1][j], sh[j]);

    if (!is_last_block(1, gridDim.x)) return;
    choose_level(1, 0, 1, P);
    lb_clean(1, 1, 2048);
}

// stage0 L2 over compact candidates + RANSAC sampling; LB: choose -> med,
// reset g_ccnt, clean
__global__ void __launch_bounds__(256)
k_tinyA(const float* __restrict__ dpri, const float* __restrict__ yout,
        int P, uint4 KP, uint4 KS) {
    __shared__ unsigned int sh[1024];
    int t = threadIdx.x;
    int gid = blockIdx.x * 256 + t;
    int stride = gridDim.x * 256;
    for (int j = t; j < 1024; j += 256) sh[j] = 0u;
    unsigned int prefix = g_sel_prefix;
    unsigned int span = (unsigned int)g_n_valid;
    bool dense = (span == (unsigned int)P);
    int ccnt = g_ccnt;
    __syncthreads();

    for (int i = gid; i < ccnt; i += stride) {
        unsigned int key = g_cand[i];
        if ((key >> 10) == prefix) atomicAdd(&sh[key & 1023u], 1u);
    }

    if (gid < SUBN) {
        if (span == 0u) { g_xsub[gid] = 0.f; g_ysub[gid] = 0.f; }
        else {
            unsigned int hb = jax_bits(KS.x, KS.y, (unsigned int)gid, SUBN);
            unsigned int lb = jax_bits(KS.z, KS.w, (unsigned int)gid, SUBN);
            unsigned int pos = randint_off(hb, lb, span);
            int si = dense ? (int)pos : g_idx[pos];
            g_xsub[gid] = dpri[si];
            g_ysub[gid] = yout[si];
        }
    }
    if (gid < ITERS) {
        unsigned int p0 = 0u, p1 = 0u;
        if (span != 0u) {
            p0 = randint_off(jax_bits(KP.x, KP.y, 2u * gid, 2u * ITERS),
                             jax_bits(KP.z, KP.w, 2u * gid, 2u * ITERS), span);
            p1 = randint_off(jax_bits(KP.x, KP.y, 2u * gid + 1u, 2u * ITERS),
                             jax_bits(KP.z, KP.w, 2u * gid + 1u, 2u * ITERS), span);
        }
        int i0 = (dense && span) ? (int)p0 : g_idx[p0];
        int i1 = (dense && span) ? (int)p1 : g_idx[p1];
        float x1 = dpri[i0], x2 = dpri[i1];
        float y1 = yout[i0], y2 = yout[i1];
        float sc = __fdiv_rn(__fsub_rn(y2, y1), __fadd_rn(__fsub_rn(x2, x1), 1e-8f));
        g_scales[gid] = sc;
        g_shifts[gid] = __fsub_rn(y1, __fmul_rn(sc, x1));
    }
    __syncthreads();
    for (int j = t; j < 1024; j += 256)
        if (sh[j]) atomicAdd(&g_hist[2][j], sh[j]);

    if (!is_last_block(2, gridDim.x)) return;
    choose_level(2, 0, 2, P);
    __syncthreads();
    if (t == 0) g_ccnt = 0;
    lb_clean(2, 2, 1024);
}

// stage1 L0: full ATOMS pass (NaN -> bin 0x3FE, above all finite; never selected)
__global__ void __launch_bounds__(256)
k_h1L0(int P) {
    __shared__ unsigned int sh[2048];
    int t = threadIdx.x;
    for (int j = t; j < 2048; j += 256) sh[j] = 0u;
    float med = g_med;
    __syncthreads();
    int s0 = blockIdx.x * CHUNK + t * 16;
    if (s0 + 16 <= P) {
        float ym[16];
#pragma unroll
        for (int j = 0; j < 4; j++) {
            float4 a = *(const float4*)(g_ymask + s0 + 4 * j);
            ym[4 * j] = a.x; ym[4 * j + 1] = a.y; ym[4 * j + 2] = a.z; ym[4 * j + 3] = a.w;
        }
#pragma unroll
        for (int k = 0; k < 16; k++) {
            unsigned int key = __float_as_uint(__fsub_rn(ym[k], med)) & 0x7FFFFFFFu;
            atomicAdd(&sh[key >> 21], 1u);
        }
    } else {
        for (int i = s0; i < P && i < s0 + 16; i++) {
            unsigned int key = __float_as_uint(__fsub_rn(g_ymask[i], med)) & 0x7FFFFFFFu;
            atomicAdd(&sh[key >> 21], 1u);
        }
    }
    __syncthreads();
    for (int j = t; j < 2048; j += 256)
        if (sh[j]) atomicAdd(&g_hist[3][j], sh[j]);

    if (!is_last_block(3, gridDim.x)) return;
    choose_level(0, 1, 3, P);
    lb_clean(3, 3, 2048);
}

// stage1 L1: hist matching prefix + compact matching keys; LB: choose L1s1
__global__ void __launch_bounds__(256)
k_h1L1c(int P) {
    __shared__ unsigned int sh[2048];
    __shared__ int wsh[8];
    __shared__ int s_base, s_tot;
    int t = threadIdx.x;
    for (int j = t; j < 2048; j += 256) sh[j] = 0u;
    float med = g_med;
    unsigned int prefix = g_sel_prefix;
    __syncthreads();
    int s0 = blockIdx.x * CHUNK + t * 16;
    unsigned int key[16];
    if (s0 + 16 <= P) {
        float ym[16];
#pragma unroll
        for (int j = 0; j < 4; j++) {
            float4 a = *(const float4*)(g_ymask + s0 + 4 * j);
            ym[4 * j] = a.x; ym[4 * j + 1] = a.y; ym[4 * j + 2] = a.z; ym[4 * j + 3] = a.w;
        }
#pragma unroll
        for (int k = 0; k < 16; k++)
            key[k] = __float_as_uint(__fsub_rn(ym[k], med)) & 0x7FFFFFFFu;
    } else {
#pragma unroll
        for (int k = 0; k < 16; k++)
            key[k] = (s0 + k < P)
                ? (__float_as_uint(__fsub_rn(g_ymask[s0 + k], med)) & 0x7FFFFFFFu)
                : 0x7FC00000u;   // NaN-class: never matches a finite prefix
    }
    int nm = 0;
    unsigned int mkeys[16];
#pragma unroll
    for (int k = 0; k < 16; k++) {
        if ((key[k] >> 21) == prefix) {
            atomicAdd(&sh[(key[k] >> 10) & 2047u], 1u);
            mkeys[nm++] = key[k];
        }
    }
    int mex = blk_scan256(nm, wsh);
    if (t == 255) s_tot = mex + nm;
    __syncthreads();
    if (t == 0) s_base = atomicAdd(&g_ccnt, s_tot);
    __syncthreads();
    for (int j = 0; j < nm; j++) g_cand[s_base + mex + j] = mkeys[j];
    __syncthreads();
    for (int j = t; j < 2048; j += 256)
        if (sh[j]) atomicAdd(&g_hist[4][j], sh[j]);

    if (!is_last_block(4, gridDim.x)) return;
    choose_level(1, 1, 4, P);
    lb_clean(4, 4, 2048);
}

// stage1 L2 over compact candidates; LB: choose -> dyn, reset g_ccnt, clean
__global__ void __launch_bounds__(256)
k_tinyB(int P) {
    __shared__ unsigned int sh[1024];
    int t = threadIdx.x;
    int gid = blockIdx.x * 256 + t;
    int stride = gridDim.x * 256;
    for (int j = t; j < 1024; j += 256) sh[j] = 0u;
    unsigned int prefix = g_sel_prefix;
    int ccnt = g_ccnt;
    __syncthreads();
    for (int i = gid; i < ccnt; i += stride) {
        unsigned int key = g_cand[i];
        if ((key >> 10) == prefix) atomicAdd(&sh[key & 1023u], 1u);
    }
    __syncthreads();
    for (int j = t; j < 1024; j += 256)
        if (sh[j]) atomicAdd(&g_hist[5][j], sh[j]);

    if (!is_last_block(5, gridDim.x)) return;
    choose_level(2, 1, 5, P);
    __syncthreads();
    if (t == 0) g_ccnt = 0;
    lb_clean(5, 5, 1024);
}

// RANSAC scoring; LB: argmax -> g_s,g_t, zero g_counts
__global__ void __launch_bounds__(256)
k_count() {
    __shared__ int wc[8][8];
    __shared__ int sc[256], si[256];
    int t = threadIdx.x;
    int hy = (blockIdx.x % 125) * 8;
    int seg = blockIdx.x / 125;
    int j0 = seg * (SUBN / 8), j1 = j0 + (SUBN / 8);
    float s[8], tv[8];
    int c[8] = {0, 0, 0, 0, 0, 0, 0, 0};
#pragma unroll
    for (int k = 0; k < 8; k++) { s[k] = g_scales[hy + k]; tv[k] = g_shifts[hy + k]; }
    float dyn = g_dyn;
    for (int j = j0 + t; j < j1; j += 256) {
        float x = g_xsub[j], yv = g_ysub[j];
#pragma unroll
        for (int k = 0; k < 8; k++) {
            float r = fabsf(__fsub_rn(__fadd_rn(__fmul_rn(s[k], x), tv[k]), yv));
            c[k] += (r < dyn) ? 1 : 0;
        }
    }
    int lane = t & 31, w = t >> 5;
#pragma unroll
    for (int k = 0; k < 8; k++) {
        int v = c[k];
        for (int o = 16; o; o >>= 1) v += __shfl_down_sync(0xffffffffu, v, o);
        if (lane == 0) wc[w][k] = v;
    }
    __syncthreads();
    if (t < 8) {
        int v = 0;
        for (int j = 0; j < 8; j++) v += wc[j][t];
        atomicAdd(&g_counts[hy + t], v);
    }

    if (!is_last_block(6, gridDim.x)) return;

    int best = -2, bidx = 0x7FFFFFFF;
    for (int i = t; i < ITERS; i += 256) {
        int cc = (g_scales[i] > 0.0f) ? g_counts[i] : -1;
        if (cc > best || (cc == best && i < bidx)) { best = cc; bidx = i; }
    }
    sc[t] = best; si[t] = bidx;
    __syncthreads();
    for (int off = 128; off; off >>= 1) {
        if (t < off) {
            if (sc[t + off] > sc[t] || (sc[t + off] == sc[t] && si[t + off] < si[t])) {
                sc[t] = sc[t + off]; si[t] = si[t + off];
            }
        }
        __syncthreads();
    }
    if (t == 0) {
        bool valid = sc[0] >= 0;
        float ss = valid ? g_scales[si[0]] : 1.0f;
        float tt = valid ? g_shifts[si[0]] : 0.0f;
        if (g_n_valid < 10) { ss = 1.0f; tt = 0.0f; }
        g_s = ss; g_t = tt;
    }
    __syncthreads();
    for (int i = t; i < ITERS; i += 256) g_counts[i] = 0;
    if (t == 0) g_done[6] = 0u;
}

// MUFU-free reciprocal: magic seed + 3 Newton (rel err ~1e-7; depth is
// stop-gradient output under 1e-3 tolerance). Loss term stays exact.
__device__ __forceinline__ float fast_rcp(float x) {
    float r = __uint_as_float(0x7EF311C3u - __float_as_uint(x));
    r = __fmul_rn(r, __fmaf_rn(-x, r, 2.0f));
    r = __fmul_rn(r, __fmaf_rn(-x, r, 2.0f));
    r = __fmul_rn(r, __fmaf_rn(-x, r, 2.0f));
    return r;
}

// outputs + loss partials; LB: final loss
__global__ void __launch_bounds__(256)
k_out(const float* __restrict__ dpri, float* __restrict__ depth_out,
      float* __restrict__ o, int P) {
    __shared__ float shf[256];
    __shared__ double shd[256];
    int t = threadIdx.x;
    float s = g_s, tt = g_t;
    float acc = 0.f;
    int s0 = blockIdx.x * CHUNK + t * 16;
    if (s0 + 16 <= P) {
        float ym[16], pp[16];
#pragma unroll
        for (int j = 0; j < 4; j++) {
            float4 a = *(const float4*)(g_ymask + s0 + 4 * j);
            float4 p = *(const float4*)(dpri + s0 + 4 * j);
            ym[4 * j] = a.x; ym[4 * j + 1] = a.y; ym[4 * j + 2] = a.z; ym[4 * j + 3] = a.w;
            pp[4 * j] = p.x; pp[4 * j + 1] = p.y; pp[4 * j + 2] = p.z; pp[4 * j + 3] = p.w;
        }
#pragma unroll
        for (int k = 0; k < 16; k++) {
            float al = __fadd_rn(__fmul_rn(s, pp[k]), tt);
            depth_out[s0 + k] = fast_rcp(fmaxf(al, 1e-4f));
            if (__float_as_uint(ym[k]) < 0x7F800000u)
                acc += fabsf(__fsub_rn(al, ym[k]));
        }
    } else {
        for (int i = s0; i < P && i < s0 + 16; i++) {
            float al = __fadd_rn(__fmul_rn(s, dpri[i]), tt);
            depth_out[i] = fast_rcp(fmaxf(al, 1e-4f));
            float ym = g_ymask[i];
            if (__float_as_uint(ym) < 0x7F800000u)
                acc += fabsf(__fsub_rn(al, ym));
        }
    }
    shf[t] = acc;
    __syncthreads();
    for (int off = 128; off; off >>= 1) {
        if (t < off) shf[t] += shf[t + off];
        __syncthreads();
    }
    if (t == 0) g_part[blockIdx.x] = shf[0];

    if (!is_last_block(7, gridDim.x)) return;

    double d = 0.0;
    for (int i = t; i < (int)gridDim.x; i += 256) d += (double)g_part[i];
    shd[t] = d;
    __syncthreads();
    for (int off = 128; off; off >>= 1) {
        if (t < off) shd[t] += shd[t + off];
        __syncthreads();
    }
    if (t == 0) {
        int n = g_n_valid;
        int denom = (n > 1) ? n : 1;
        float l1 = (float)shd[0] / (float)denom;
        float loss = __fmul_rn(0.5f, l1);
        if (n < 100) loss = 0.0f;
        o[0] = loss;
        g_done[7] = 0u;
    }
}

// ------------------ launch ------------------
extern "C" void kernel_launch(void* const* d_in, const int* in_sizes, int n_in,
                              void* d_out, int out_size) {
    const float* dren = (const float*)d_in[0];
    const float* dpri = (const float*)d_in[1];
    float* o = (float*)d_out;
    int P = in_sizes[0];
    float* yout  = o + 1;
    float* dout2 = o + 1 + P;

    unsigned int kk[4], kp[4], ks[4];
    jax_split2_host(0u, 42u, kk);
    jax_split2_host(kk[0], kk[1], kp);
    jax_split2_host(kk[2], kk[3], ks);
    uint4 KP = make_uint4(kp[0], kp[1], kp[2], kp[3]);
    uint4 KS = make_uint4(ks[0], ks[1], ks[2], ks[3]);

    int NB = (P + CHUNK - 1) / CHUNK;   // 512 for P=2M

    k_fused1<<<NB, 256>>>(dren, yout, P, NB);
    k_fused2<<<NB, 256>>>(P);
    k_tinyA<<<256, 256>>>(dpri, yout, P, KP, KS);
    k_h1L0<<<NB, 256>>>(P);
    k_h1L1c<<<NB, 256>>>(P);
    k_tinyB<<<256, 256>>>(P);
    k_count<<<CNTB, 256>>>();
    k_out<<<NB, 256>>>(dpri, dout2, o, P);
}